// round 7
// baseline (speedup 1.0000x reference)
#include <cuda_runtime.h>
#include <cuda_bf16.h>

#define Bn 8
#define Sn 512
#define Kn 16
#define Rr 8            // output rows per block
#define NT 256          // threads per block (each owns cols x and x+256)
#define SW (Sn + 4)     // padded shared row width (cols 0 and Sn+1 are zero)
#define EMPTY_DIST 362.1f
#define FAR_COORD 1.0e18f

// Persistent scratch (no allocations allowed). Starts zeroed (.bss);
// the last main block resets counters after use -> deterministic replays.
__device__ float    g_py[Bn][Kn];
__device__ float    g_px[Bn][Kn];
__device__ int      g_cnt[Bn];
__device__ unsigned g_maxbits[Bn];
__device__ double   g_numer[Bn];
__device__ double   g_gradsum;
__device__ unsigned g_done;

// ---------------------------------------------------------------------------
// Kernel 1: collect nonzero label pixels. Wide grid: (slices, Bn).
// ---------------------------------------------------------------------------
#define CSLICES 64
__global__ __launch_bounds__(256) void collect_kernel(const float* __restrict__ pt) {
    const int b = blockIdx.y;
    const int slice = blockIdx.x;
    const int n4_per_slice = (Sn * Sn / 4) / CSLICES;      // 1024 float4
    const float4* p = (const float4*)(pt + (size_t)b * Sn * Sn) + slice * n4_per_slice;
    for (int i = threadIdx.x; i < n4_per_slice; i += 256) {
        float4 v = p[i];
        if (v.x != 0.f || v.y != 0.f || v.z != 0.f || v.w != 0.f) {
            float vv[4] = {v.x, v.y, v.z, v.w};
            int base_idx = (slice * n4_per_slice + i) * 4;
            #pragma unroll
            for (int j = 0; j < 4; j++) {
                if (vv[j] != 0.f) {
                    int idx = base_idx + j;
                    int slot = atomicAdd(&g_cnt[b], 1);
                    if (slot < Kn) {
                        g_py[b][slot] = (float)(idx / Sn);
                        g_px[b][slot] = (float)(idx % Sn);
                    }
                }
            }
        }
    }
}

// ---------------------------------------------------------------------------
// Kernel 2: fused distance + sobel + reductions + finalize.
// grid (Sn/Rr, Bn), block NT threads, 2 strided columns per thread.
// ---------------------------------------------------------------------------
__global__ __launch_bounds__(NT, 6) void main_kernel(const float* __restrict__ pred,
                                                     const float* __restrict__ ori,
                                                     float* __restrict__ out) {
    __shared__ float s_img[Rr + 2][SW];     // cols 0 and Sn+1 are zero
    __shared__ float s_py[Kn], s_px[Kn];
    __shared__ int   s_cnt;
    __shared__ float sh_s[8], sh_g[8], sh_m[8];

    const int y0 = blockIdx.x * Rr;
    const int b  = blockIdx.y;
    const int x  = threadIdx.x;

    const float* __restrict__ pb = pred + b * (Sn * Sn);
    const float* __restrict__ ob = ori  + b * (Sn * Sn);

    if (x < Kn) {
        int c = g_cnt[b]; c = (c > Kn) ? Kn : c;
        s_py[x] = (x < c) ? g_py[b][x] : FAR_COORD;
        s_px[x] = (x < c) ? g_px[b][x] : FAR_COORD;
        if (x == 0) s_cnt = c;
    }
    if (x < 2) {
        int col = (x == 0) ? 0 : (Sn + 1);
        #pragma unroll
        for (int rr = 0; rr < Rr + 2; rr++) s_img[rr][col] = 0.f;
    }

    // --- phase 1: loads issued first (latency hidden by later compute) ---
    float pv0[Rr], pv1[Rr];
    #pragma unroll
    for (int rr = 0; rr < Rr + 2; rr++) {
        int yy = y0 - 1 + rr;
        float p0 = 0.f, v0 = 0.f, p1 = 0.f, v1 = 0.f;
        if (yy >= 0 && yy < Sn) {
            int o = yy * Sn + x;
            p0 = __ldg(pb + o);        v0 = p0 * __ldg(ob + o);
            p1 = __ldg(pb + o + NT);   v1 = p1 * __ldg(ob + o + NT);
        }
        s_img[rr][x + 1]      = v0;
        s_img[rr][x + NT + 1] = v1;
        if (rr >= 1 && rr <= Rr) { pv0[rr - 1] = p0; pv1[rr - 1] = p1; }
    }
    __syncthreads();

    const int cnt = s_cnt;
    const float fy0 = (float)y0;
    float vsum = 0.f, vmax = 0.f;

    // --- phase 2: distance per column (m[] lifetime ends before sobel) ---
    #pragma unroll
    for (int cc = 0; cc < 2; cc++) {
        const float fx = (float)(x + cc * NT);
        float m[Rr];
        #pragma unroll
        for (int r = 0; r < Rr; r++) m[r] = 3.0e38f;
        #pragma unroll
        for (int i = 0; i < Kn; i++) {
            float dxv = fx - s_px[i];
            float dy0 = fy0 - s_py[i];
            float c = fmaf(dy0, dy0, dxv * dxv);
            float e = dy0 + dy0;
            #pragma unroll
            for (int r = 0; r < Rr; r++)
                m[r] = fminf(m[r], fmaf((float)r, e, c));
        }
        #pragma unroll
        for (int r = 0; r < Rr; r++) {
            float d2 = m[r] + (float)(r * r);
            float dist = (cnt > 0) ? sqrtf(d2) : EMPTY_DIST;
            float dd = (dist > 1.0f) ? (dist - 1.0f) : 0.f;
            vsum += ((cc == 0) ? pv0[r] : pv1[r]) * dd;
            vmax = fmaxf(vmax, dd);
        }
    }

    // --- phase 3: rolling-window sobel per column ---
    float gsum = 0.f;
    #pragma unroll
    for (int cc = 0; cc < 2; cc++) {
        const int col = x + cc * NT;
        const bool xok = (col >= 1) && (col <= Sn - 2);

        float a0l = s_img[0][col], a0c = s_img[0][col + 1], a0r = s_img[0][col + 2];
        float a1l = s_img[1][col], a1c = s_img[1][col + 1], a1r = s_img[1][col + 2];

        #pragma unroll
        for (int r = 0; r < Rr; r++) {
            const int y = y0 + r;
            float a2l = s_img[r + 2][col], a2c = s_img[r + 2][col + 1], a2r = s_img[r + 2][col + 2];

            if (xok && y >= 1 && y <= Sn - 2) {
                float g0 = (a0r - a0l) + 2.f * (a1r - a1l) + (a2r - a2l);
                float g1 = (a0l - a2l) + 2.f * (a0c - a2c) + (a0r - a2r);
                float g2 = 2.f * (a0l - a2r) + (a0c - a2c) + (a1l - a1r);
                float g3 = (a0c - a2c) + 2.f * (a0r - a2l) + (a1r - a1l);
                gsum += fmaxf(fmaxf(fabsf(g0), fabsf(g1)), fmaxf(fabsf(g2), fabsf(g3)));
            }

            a0l = a1l; a0c = a1c; a0r = a1r;
            a1l = a2l; a1c = a2c; a1r = a2r;
        }
    }

    // --- block reduction: sum(vsum), sum(gsum), max(vmax) ---
    #pragma unroll
    for (int o = 16; o > 0; o >>= 1) {
        vsum += __shfl_down_sync(0xffffffffu, vsum, o);
        gsum += __shfl_down_sync(0xffffffffu, gsum, o);
        vmax = fmaxf(vmax, __shfl_down_sync(0xffffffffu, vmax, o));
    }
    const int wid = x >> 5, lane = x & 31;
    if (lane == 0) { sh_s[wid] = vsum; sh_g[wid] = gsum; sh_m[wid] = vmax; }
    __syncthreads();
    if (wid == 0) {
        vsum = (lane < 8) ? sh_s[lane] : 0.f;
        gsum = (lane < 8) ? sh_g[lane] : 0.f;
        vmax = (lane < 8) ? sh_m[lane] : 0.f;
        #pragma unroll
        for (int o = 4; o > 0; o >>= 1) {
            vsum += __shfl_down_sync(0xffffffffu, vsum, o);
            gsum += __shfl_down_sync(0xffffffffu, gsum, o);
            vmax = fmaxf(vmax, __shfl_down_sync(0xffffffffu, vmax, o));
        }
        if (lane == 0) {
            atomicAdd(&g_numer[b], (double)vsum);
            atomicAdd(&g_gradsum, (double)gsum);
            atomicMax(&g_maxbits[b], __float_as_uint(vmax));

            __threadfence();
            unsigned ticket = atomicAdd(&g_done, 1u);
            const unsigned total = (Sn / Rr) * Bn;
            if (ticket == total - 1u) {
                double acc = 0.0;
                #pragma unroll
                for (int bb = 0; bb < Bn; bb++) {
                    float mx = __uint_as_float(g_maxbits[bb]);
                    acc += g_numer[bb] / (double)mx;
                    g_numer[bb] = 0.0;
                    g_maxbits[bb] = 0u;
                    g_cnt[bb] = 0;
                }
                const double denom = (double)Sn * (double)Sn * (double)Bn;
                out[0] = (float)(acc / denom);
                out[1] = (float)(g_gradsum / denom);
                g_gradsum = 0.0;
                g_done = 0u;
                __threadfence();
            }
        }
    }
}

extern "C" void kernel_launch(void* const* d_in, const int* in_sizes, int n_in,
                              void* d_out, int out_size) {
    const float* pred = (const float*)d_in[0];
    const float* ptl  = (const float*)d_in[1];
    const float* ori  = (const float*)d_in[2];
    float* out = (float*)d_out;

    collect_kernel<<<dim3(CSLICES, Bn), 256>>>(ptl);
    main_kernel<<<dim3(Sn / Rr, Bn), NT>>>(pred, ori, out);
}

// round 8
// speedup vs baseline: 1.8517x; 1.8517x over previous
#include <cuda_runtime.h>
#include <cuda_bf16.h>

#define Bn 8
#define Sn 512
#define Kn 16
#define Rr 8            // output rows per block
#define SW (Sn + 4)     // padded shared row width (cols 0 and Sn+1 are zero)
#define EMPTY_DIST 362.1f
#define FAR_COORD 1.0e18f

// Persistent scratch (no allocations allowed). Starts zeroed (.bss);
// the last main block resets counters after use -> deterministic replays.
__device__ float    g_py[Bn][Kn];
__device__ float    g_px[Bn][Kn];
__device__ int      g_cnt[Bn];
__device__ unsigned g_maxbits[Bn];
__device__ double   g_numer[Bn];
__device__ double   g_gradsum;
__device__ unsigned g_done;

// ---------------------------------------------------------------------------
// Kernel 1: collect nonzero label pixels. Wide grid: (slices, Bn).
// ---------------------------------------------------------------------------
#define CSLICES 64
__global__ __launch_bounds__(256) void collect_kernel(const float* __restrict__ pt) {
    const int b = blockIdx.y;
    const int slice = blockIdx.x;
    const int n4_per_slice = (Sn * Sn / 4) / CSLICES;      // 1024 float4
    const float4* p = (const float4*)(pt + (size_t)b * Sn * Sn) + slice * n4_per_slice;
    for (int i = threadIdx.x; i < n4_per_slice; i += 256) {
        float4 v = p[i];
        if (v.x != 0.f || v.y != 0.f || v.z != 0.f || v.w != 0.f) {
            float vv[4] = {v.x, v.y, v.z, v.w};
            int base_idx = (slice * n4_per_slice + i) * 4;
            #pragma unroll
            for (int j = 0; j < 4; j++) {
                if (vv[j] != 0.f) {
                    int idx = base_idx + j;
                    int slot = atomicAdd(&g_cnt[b], 1);
                    if (slot < Kn) {
                        g_py[b][slot] = (float)(idx / Sn);
                        g_px[b][slot] = (float)(idx % Sn);
                    }
                }
            }
        }
    }
}

// ---------------------------------------------------------------------------
// Kernel 2: fused distance + sobel + reductions + finalize.
// grid (Sn/Rr, Bn), block 512 threads, 3 blocks/SM (best measured shape).
// ---------------------------------------------------------------------------
__global__ __launch_bounds__(Sn, 3) void main_kernel(const float* __restrict__ pred,
                                                     const float* __restrict__ ori,
                                                     float* __restrict__ out) {
    __shared__ float s_img[Rr + 2][SW];     // cols 0 and Sn+1 are zero
    __shared__ float s_py[Kn], s_px[Kn];
    __shared__ int   s_cnt;
    __shared__ float sh_s[16], sh_g[16], sh_m[16];

    const int y0 = blockIdx.x * Rr;
    const int b  = blockIdx.y;
    const int x  = threadIdx.x;

    const float* __restrict__ pb = pred + b * (Sn * Sn);
    const float* __restrict__ ob = ori  + b * (Sn * Sn);

    if (x < Kn) {
        int c = g_cnt[b]; c = (c > Kn) ? Kn : c;
        s_py[x] = (x < c) ? g_py[b][x] : FAR_COORD;
        s_px[x] = (x < c) ? g_px[b][x] : FAR_COORD;
        if (x == 0) s_cnt = c;
    }
    if (x < 2) {
        int col = (x == 0) ? 0 : (Sn + 1);
        #pragma unroll
        for (int rr = 0; rr < Rr + 2; rr++) s_img[rr][col] = 0.f;
    }

    // --- phase 1: global loads issued first (latency covered by later math) ---
    float pv[Rr];
    #pragma unroll
    for (int rr = 0; rr < Rr + 2; rr++) {
        int yy = y0 - 1 + rr;
        float pval = 0.f, v = 0.f;
        if (yy >= 0 && yy < Sn) {
            int o = yy * Sn + x;
            pval = __ldg(pb + o);
            v = pval * __ldg(ob + o);
        }
        s_img[rr][x + 1] = v;
        if (rr >= 1 && rr <= Rr) pv[rr - 1] = pval;
    }
    __syncthreads();

    const int cnt = s_cnt;
    const float fx  = (float)x;
    const float fy0 = (float)y0;

    // --- phase 2a: exact per-warp point culling over the warp's 32xRr tile ---
    // lb_i = squared dist from tile AABB to point i; ub_i = squared dist to
    // farthest tile corner. Any i with lb_i > min_j ub_j can never be the
    // per-pixel argmin in this tile -> droppable with bit-identical results.
    unsigned keep;
    {
        const int lane = x & 31;
        const float x0f = (float)(x & ~31);
        const float x1f = x0f + 31.0f;
        const float y1f = fy0 + (float)(Rr - 1);
        float lb = 3.0e38f, ubi = 3.0e38f;
        if (lane < Kn) {
            float pxv = s_px[lane], pyv = s_py[lane];
            float dxl = x0f - pxv, dxr = pxv - x1f;          // one of these <= 0
            float dxm = fmaxf(0.f, fmaxf(dxl, dxr));
            float dxM = fmaxf(fabsf(dxl), fabsf(x1f - pxv));
            float dyl = fy0 - pyv, dyr = pyv - y1f;
            float dym = fmaxf(0.f, fmaxf(dyl, dyr));
            float dyM = fmaxf(fabsf(dyl), fabsf(y1f - pyv));
            lb  = fmaf(dxm, dxm, dym * dym);
            ubi = fmaf(dxM, dxM, dyM * dyM);
        }
        float ub = ubi;
        #pragma unroll
        for (int o = 16; o > 0; o >>= 1)
            ub = fminf(ub, __shfl_xor_sync(0xffffffffu, ub, o));
        keep = __ballot_sync(0xffffffffu, lb <= ub);
    }

    // --- phase 2b: distance mins over surviving points only (warp-uniform) ---
    float m[Rr];
    #pragma unroll
    for (int r = 0; r < Rr; r++) m[r] = 3.0e38f;

    unsigned mask = keep;
    while (mask) {
        int i = __ffs(mask) - 1;
        mask &= mask - 1;
        float dxv = fx - s_px[i];
        float dy0 = fy0 - s_py[i];
        float c = fmaf(dy0, dy0, dxv * dxv);
        float e = dy0 + dy0;
        #pragma unroll
        for (int r = 0; r < Rr; r++)
            m[r] = fminf(m[r], fmaf((float)r, e, c));       // d2(r) = m + r^2 later
    }

    float vsum = 0.f, vmax = 0.f;
    #pragma unroll
    for (int r = 0; r < Rr; r++) {
        float d2 = m[r] + (float)(r * r);
        float dist = (cnt > 0) ? sqrtf(d2) : EMPTY_DIST;
        float dd = (dist > 1.0f) ? (dist - 1.0f) : 0.f;
        vsum += pv[r] * dd;
        vmax = fmaxf(vmax, dd);
    }

    // --- phase 3: rolling-window sobel with shared subexpressions ---
    float gsum = 0.f;
    const bool xok = (x >= 1) && (x <= Sn - 2);

    float a0l = s_img[0][x], a0c = s_img[0][x + 1], a0r = s_img[0][x + 2];
    float a1l = s_img[1][x],                        a1r = s_img[1][x + 2];

    #pragma unroll
    for (int r = 0; r < Rr; r++) {
        const int y = y0 + r;
        float a2l = s_img[r + 2][x], a2c = s_img[r + 2][x + 1], a2r = s_img[r + 2][x + 2];

        if (xok && y >= 1 && y <= Sn - 2) {
            float t = a0c - a2c;     // n01 - n21
            float u = a1r - a1l;     // n12 - n10
            float p = a0r - a2l;     // n02 - n20
            float q = a0l - a2r;     // n00 - n22
            float g0 = fmaf(2.f, u, p - q);
            float g1 = fmaf(2.f, t, p + q);
            float g2 = fmaf(2.f, q, t - u);
            float g3 = fmaf(2.f, p, t + u);
            gsum += fmaxf(fmaxf(fabsf(g0), fabsf(g1)), fmaxf(fabsf(g2), fabsf(g3)));
        }

        a0l = a1l; a0c = s_img[r + 1][x + 1]; a0r = a1r;
        a1l = a2l;                            a1r = a2r;
    }

    // --- block reduction: sum(vsum), sum(gsum), max(vmax) ---
    #pragma unroll
    for (int o = 16; o > 0; o >>= 1) {
        vsum += __shfl_down_sync(0xffffffffu, vsum, o);
        gsum += __shfl_down_sync(0xffffffffu, gsum, o);
        vmax = fmaxf(vmax, __shfl_down_sync(0xffffffffu, vmax, o));
    }
    const int wid = x >> 5, lane = x & 31;
    if (lane == 0) { sh_s[wid] = vsum; sh_g[wid] = gsum; sh_m[wid] = vmax; }
    __syncthreads();
    if (wid == 0) {
        vsum = (lane < 16) ? sh_s[lane] : 0.f;
        gsum = (lane < 16) ? sh_g[lane] : 0.f;
        vmax = (lane < 16) ? sh_m[lane] : 0.f;
        #pragma unroll
        for (int o = 8; o > 0; o >>= 1) {
            vsum += __shfl_down_sync(0xffffffffu, vsum, o);
            gsum += __shfl_down_sync(0xffffffffu, gsum, o);
            vmax = fmaxf(vmax, __shfl_down_sync(0xffffffffu, vmax, o));
        }
        if (lane == 0) {
            atomicAdd(&g_numer[b], (double)vsum);
            atomicAdd(&g_gradsum, (double)gsum);
            atomicMax(&g_maxbits[b], __float_as_uint(vmax));

            __threadfence();
            unsigned ticket = atomicAdd(&g_done, 1u);
            const unsigned total = (Sn / Rr) * Bn;
            if (ticket == total - 1u) {
                double acc = 0.0;
                #pragma unroll
                for (int bb = 0; bb < Bn; bb++) {
                    float mx = __uint_as_float(g_maxbits[bb]);
                    acc += g_numer[bb] / (double)mx;
                    g_numer[bb] = 0.0;
                    g_maxbits[bb] = 0u;
                    g_cnt[bb] = 0;
                }
                const double denom = (double)Sn * (double)Sn * (double)Bn;
                out[0] = (float)(acc / denom);
                out[1] = (float)(g_gradsum / denom);
                g_gradsum = 0.0;
                g_done = 0u;
                __threadfence();
            }
        }
    }
}

extern "C" void kernel_launch(void* const* d_in, const int* in_sizes, int n_in,
                              void* d_out, int out_size) {
    const float* pred = (const float*)d_in[0];
    const float* ptl  = (const float*)d_in[1];
    const float* ori  = (const float*)d_in[2];
    float* out = (float*)d_out;

    collect_kernel<<<dim3(CSLICES, Bn), 256>>>(ptl);
    main_kernel<<<dim3(Sn / Rr, Bn), Sn>>>(pred, ori, out);
}

// round 9
// speedup vs baseline: 1.8767x; 1.0135x over previous
#include <cuda_runtime.h>
#include <cuda_bf16.h>

#define Bn 8
#define Sn 512
#define Kn 16
#define Rr 8            // output rows per block
#define SW (Sn + 4)     // padded shared row width (cols 0 and Sn+1 are zero)
#define EMPTY_DIST 362.1f
#define FAR_COORD 1.0e18f

// Persistent scratch (no allocations allowed). Starts zeroed (.bss);
// the last main block resets counters after use -> deterministic replays.
__device__ float    g_py[Bn][Kn];
__device__ float    g_px[Bn][Kn];
__device__ int      g_cnt[Bn];
__device__ unsigned g_maxbits[Bn];
__device__ double   g_numer[Bn];
__device__ double   g_gradsum;
__device__ unsigned g_done;

// ---------------------------------------------------------------------------
// Kernel 1: collect nonzero label pixels. Wide grid: (slices, Bn).
// ---------------------------------------------------------------------------
#define CSLICES 64
__global__ __launch_bounds__(256) void collect_kernel(const float* __restrict__ pt) {
    const int b = blockIdx.y;
    const int slice = blockIdx.x;
    const int n4_per_slice = (Sn * Sn / 4) / CSLICES;      // 1024 float4
    const float4* p = (const float4*)(pt + (size_t)b * Sn * Sn) + slice * n4_per_slice;
    for (int i = threadIdx.x; i < n4_per_slice; i += 256) {
        float4 v = p[i];
        if (v.x != 0.f || v.y != 0.f || v.z != 0.f || v.w != 0.f) {
            float vv[4] = {v.x, v.y, v.z, v.w};
            int base_idx = (slice * n4_per_slice + i) * 4;
            #pragma unroll
            for (int j = 0; j < 4; j++) {
                if (vv[j] != 0.f) {
                    int idx = base_idx + j;
                    int slot = atomicAdd(&g_cnt[b], 1);
                    if (slot < Kn) {
                        g_py[b][slot] = (float)(idx / Sn);
                        g_px[b][slot] = (float)(idx % Sn);
                    }
                }
            }
        }
    }
}

// ---------------------------------------------------------------------------
// Kernel 2: fused distance + sobel + reductions + finalize.
// grid (Sn/Rr, Bn), block 512 threads, 3 blocks/SM.
// Order: global loads -> (cull + distance, no smem dep) -> barrier -> sobel,
// so the distance math overlaps the other warps' load latency.
// ---------------------------------------------------------------------------
__global__ __launch_bounds__(Sn, 3) void main_kernel(const float* __restrict__ pred,
                                                     const float* __restrict__ ori,
                                                     float* __restrict__ out) {
    __shared__ float s_img[Rr + 2][SW];     // cols 0 and Sn+1 are zero
    __shared__ float sh_s[16], sh_g[16], sh_m[16];

    const int y0 = blockIdx.x * Rr;
    const int b  = blockIdx.y;
    const int x  = threadIdx.x;
    const int lane = x & 31;

    const float* __restrict__ pb = pred + b * (Sn * Sn);
    const float* __restrict__ ob = ori  + b * (Sn * Sn);

    // point coords in registers (lane<16), broadcast later via shfl. L2-hot.
    int cload = 0;
    float pxv = FAR_COORD, pyv = FAR_COORD;
    if (lane == 0) cload = g_cnt[b];
    const int cnt = min(__shfl_sync(0xffffffffu, cload, 0), Kn);
    if (lane < Kn) {
        if (lane < cnt) { pxv = g_px[b][lane]; pyv = g_py[b][lane]; }
    }

    if (x < 2) {
        int col = (x == 0) ? 0 : (Sn + 1);
        #pragma unroll
        for (int rr = 0; rr < Rr + 2; rr++) s_img[rr][col] = 0.f;
    }

    // --- phase 1: global loads + smem stores ---
    float pv[Rr];
    #pragma unroll
    for (int rr = 0; rr < Rr + 2; rr++) {
        int yy = y0 - 1 + rr;
        float pval = 0.f, v = 0.f;
        if (yy >= 0 && yy < Sn) {
            int o = yy * Sn + x;
            pval = __ldg(pb + o);
            v = pval * __ldg(ob + o);
        }
        s_img[rr][x + 1] = v;
        if (rr >= 1 && rr <= Rr) pv[rr - 1] = pval;
    }

    const float fx  = (float)x;
    const float fy0 = (float)y0;

    // --- phase 2a: exact per-warp point culling over the warp's 32xRr tile ---
    unsigned keep;
    {
        const float x0f = (float)(x & ~31);
        const float x1f = x0f + 31.0f;
        const float y1f = fy0 + (float)(Rr - 1);
        float lb = 3.0e38f, ubi = 3.0e38f;
        if (lane < Kn) {
            float dxl = x0f - pxv, dxr = pxv - x1f;
            float dxm = fmaxf(0.f, fmaxf(dxl, dxr));
            float dxM = fmaxf(fabsf(dxl), fabsf(x1f - pxv));
            float dyl = fy0 - pyv, dyr = pyv - y1f;
            float dym = fmaxf(0.f, fmaxf(dyl, dyr));
            float dyM = fmaxf(fabsf(dyl), fabsf(y1f - pyv));
            lb  = fmaf(dxm, dxm, dym * dym);
            ubi = fmaf(dxM, dxM, dyM * dyM);
        }
        float ub = ubi;
        #pragma unroll
        for (int o = 16; o > 0; o >>= 1)
            ub = fminf(ub, __shfl_xor_sync(0xffffffffu, ub, o));
        keep = __ballot_sync(0xffffffffu, lb <= ub);
    }

    // --- phase 2b: distance mins over surviving points (shfl-broadcast) ---
    float m[Rr];
    #pragma unroll
    for (int r = 0; r < Rr; r++) m[r] = 3.0e38f;

    unsigned mask = keep;
    while (mask) {
        int i = __ffs(mask) - 1;
        mask &= mask - 1;
        float px_i = __shfl_sync(0xffffffffu, pxv, i);
        float py_i = __shfl_sync(0xffffffffu, pyv, i);
        float dxv = fx - px_i;
        float dy0 = fy0 - py_i;
        float c = fmaf(dy0, dy0, dxv * dxv);
        float e = dy0 + dy0;
        #pragma unroll
        for (int r = 0; r < Rr; r++)
            m[r] = fminf(m[r], fmaf((float)r, e, c));       // d2(r) = m + r^2 later
    }

    float vsum = 0.f, vmax = 0.f;
    #pragma unroll
    for (int r = 0; r < Rr; r++) {
        float d2 = m[r] + (float)(r * r);
        float dist = (cnt > 0) ? sqrtf(d2) : EMPTY_DIST;
        float dd = (dist > 1.0f) ? (dist - 1.0f) : 0.f;
        vsum += pv[r] * dd;
        vmax = fmaxf(vmax, dd);
    }

    __syncthreads();

    // --- phase 3: rolling-window sobel with shared subexpressions ---
    float gsum = 0.f;
    const bool xok = (x >= 1) && (x <= Sn - 2);

    float a0l = s_img[0][x], a0c = s_img[0][x + 1], a0r = s_img[0][x + 2];
    float a1l = s_img[1][x],                        a1r = s_img[1][x + 2];

    #pragma unroll
    for (int r = 0; r < Rr; r++) {
        const int y = y0 + r;
        float a2l = s_img[r + 2][x], a2c = s_img[r + 2][x + 1], a2r = s_img[r + 2][x + 2];

        if (xok && y >= 1 && y <= Sn - 2) {
            float t = a0c - a2c;     // n01 - n21
            float u = a1r - a1l;     // n12 - n10
            float p = a0r - a2l;     // n02 - n20
            float q = a0l - a2r;     // n00 - n22
            float g0 = fmaf(2.f, u, p - q);
            float g1 = fmaf(2.f, t, p + q);
            float g2 = fmaf(2.f, q, t - u);
            float g3 = fmaf(2.f, p, t + u);
            gsum += fmaxf(fmaxf(fabsf(g0), fabsf(g1)), fmaxf(fabsf(g2), fabsf(g3)));
        }

        a0l = a1l; a0c = s_img[r + 1][x + 1]; a0r = a1r;
        a1l = a2l;                            a1r = a2r;
    }

    // --- block reduction: sum(vsum), sum(gsum), max(vmax) ---
    #pragma unroll
    for (int o = 16; o > 0; o >>= 1) {
        vsum += __shfl_down_sync(0xffffffffu, vsum, o);
        gsum += __shfl_down_sync(0xffffffffu, gsum, o);
        vmax = fmaxf(vmax, __shfl_down_sync(0xffffffffu, vmax, o));
    }
    const int wid = x >> 5;
    if (lane == 0) { sh_s[wid] = vsum; sh_g[wid] = gsum; sh_m[wid] = vmax; }
    __syncthreads();
    if (wid == 0) {
        vsum = (lane < 16) ? sh_s[lane] : 0.f;
        gsum = (lane < 16) ? sh_g[lane] : 0.f;
        vmax = (lane < 16) ? sh_m[lane] : 0.f;
        #pragma unroll
        for (int o = 8; o > 0; o >>= 1) {
            vsum += __shfl_down_sync(0xffffffffu, vsum, o);
            gsum += __shfl_down_sync(0xffffffffu, gsum, o);
            vmax = fmaxf(vmax, __shfl_down_sync(0xffffffffu, vmax, o));
        }
        if (lane == 0) {
            atomicAdd(&g_numer[b], (double)vsum);
            atomicAdd(&g_gradsum, (double)gsum);
            atomicMax(&g_maxbits[b], __float_as_uint(vmax));

            __threadfence();
            unsigned ticket = atomicAdd(&g_done, 1u);
            const unsigned total = (Sn / Rr) * Bn;
            if (ticket == total - 1u) {
                double acc = 0.0;
                #pragma unroll
                for (int bb = 0; bb < Bn; bb++) {
                    float mx = __uint_as_float(g_maxbits[bb]);
                    acc += g_numer[bb] / (double)mx;
                    g_numer[bb] = 0.0;
                    g_maxbits[bb] = 0u;
                    g_cnt[bb] = 0;
                }
                const double denom = (double)Sn * (double)Sn * (double)Bn;
                out[0] = (float)(acc / denom);
                out[1] = (float)(g_gradsum / denom);
                g_gradsum = 0.0;
                g_done = 0u;
                __threadfence();
            }
        }
    }
}

extern "C" void kernel_launch(void* const* d_in, const int* in_sizes, int n_in,
                              void* d_out, int out_size) {
    const float* pred = (const float*)d_in[0];
    const float* ptl  = (const float*)d_in[1];
    const float* ori  = (const float*)d_in[2];
    float* out = (float*)d_out;

    collect_kernel<<<dim3(CSLICES, Bn), 256>>>(ptl);
    main_kernel<<<dim3(Sn / Rr, Bn), Sn>>>(pred, ori, out);
}